// round 14
// baseline (speedup 1.0000x reference)
#include <cuda_runtime.h>

#define BB  16
#define LL  128
#define LRR 128
#define VV  32000
#define NONE 0x7fffffff

// Scratch (no allocations allowed anywhere)
__device__ float    g_probs[BB * LL * LRR];   // [b][j][i] — probs[b,0,i,j] in ref notation
__device__ int      g_hard[BB * LL];          // argmax per (b,j)
__device__ float    g_partial[BB];            // per-batch weighted prob sum
__device__ unsigned g_fin = 0;                // k2 last-block counter (self-resetting)

// Labels-dtype detect: int64 LE => every odd 32-bit word is a zero high half.
__device__ __forceinline__ void detect_is64(const int* __restrict__ lab_raw,
                                            int t, int* s_is64) {
    if (t < 32) {
        int ok  = (lab_raw[2 * t + 1] == 0);
        int all = __all_sync(0xffffffffu, ok);
        if (t == 0) *s_is64 = all;
    }
}

// ===== k1: r11 version verbatim (measured 6.97 TB/s — at the HBM ceiling) =====
__global__ __launch_bounds__(256) void k1(const float* __restrict__ logits,
                                          const int* __restrict__ lab_raw) {
    const int row  = blockIdx.x;          // b*LL + j
    const int b    = row >> 7;
    const int t    = threadIdx.x;
    const int w    = t >> 5, lane = t & 31;
    const float* __restrict__ base = logits + (size_t)row * VV;

    __shared__ float s_s[8];
    __shared__ float s_v[8];
    __shared__ int   s_i[8];
    __shared__ int   s_lab[LRR];
    __shared__ float s_inv;
    __shared__ int   s_is64;

    detect_is64(lab_raw, t, &s_is64);
    __syncthreads();
    if (t < LRR) {
        s_lab[t] = s_is64 ? lab_raw[(b * LRR + t) * 2] : lab_raw[b * LRR + t];
    }

    float acc0 = 0.0f, acc1 = 0.0f;
    float vmax  = -3.0e38f;
    int   kbest = t;                       // winning quad index (exact elem found later)
    const float4* b4 = (const float4*)base;
    #pragma unroll 4
    for (int k = t; k < VV / 4; k += 256) {
        float4 v = __ldcs(&b4[k]);           // streaming load: evict-first in L2
        acc0 += __expf(v.x) + __expf(v.y);   // MUFU.EX2 path
        acc1 += __expf(v.z) + __expf(v.w);
        float m = fmaxf(fmaxf(v.x, v.y), fmaxf(v.z, v.w));
        bool upd = m > vmax;               // strict > keeps earliest quad (first occurrence)
        kbest = upd ? k : kbest;
        vmax  = upd ? m : vmax;
    }
    float acc = acc0 + acc1;

    // Reconstruct exact element index once
    int imax;
    {
        float4 v = __ldg(&b4[kbest]);
        int i0 = kbest << 2;
        imax = (v.x == vmax) ? i0 : (v.y == vmax) ? i0 + 1
             : (v.z == vmax) ? i0 + 2 : i0 + 3;
    }

    // warp reduce: sum + (max, first-index) — tie -> smaller global index
    #pragma unroll
    for (int off = 16; off; off >>= 1) {
        acc += __shfl_down_sync(0xffffffffu, acc, off);
        float ov = __shfl_down_sync(0xffffffffu, vmax, off);
        int   oi = __shfl_down_sync(0xffffffffu, imax, off);
        if (ov > vmax || (ov == vmax && oi < imax)) { vmax = ov; imax = oi; }
    }
    if (lane == 0) { s_s[w] = acc; s_v[w] = vmax; s_i[w] = imax; }
    __syncthreads();
    if (t == 0) {
        float ts = s_s[0], tv = s_v[0];
        int   ti = s_i[0];
        #pragma unroll
        for (int q = 1; q < 8; q++) {
            ts += s_s[q];
            if (s_v[q] > tv || (s_v[q] == tv && s_i[q] < ti)) { tv = s_v[q]; ti = s_i[q]; }
        }
        s_inv = 1.0f / ts;
        g_hard[row] = ti;
    }
    __syncthreads();
    if (t < LRR) {
        // probs[b,0,i=t,j] = exp(logit[label]) / sumexp ; coalesced store [b][j][i]
        g_probs[row * LRR + t] = __expf(__ldg(&base[s_lab[t]])) * s_inv;
    }
}

// ===== k2: PDL + front-issued probs loads + vectorized weight phase =====
// The 16 per-thread probs values are independent of the sudoku -> issue them
// as 4x LDG.128 right after gridsync; their L2 latency hides under the scan.
__global__ __launch_bounds__(1024) void k2(const int* __restrict__ lab_raw,
                                           float* __restrict__ out) {
    const int b = blockIdx.x;
    const int t = threadIdx.x;

    __shared__ int           s_hard[LL];
    __shared__ int           s_lab[LRR];
    __shared__ int           s_fj[LRR];
    __shared__ int           s_colwin[LL];
    __shared__ unsigned char s_sel[LRR];
    __shared__ float         s_red[32];
    __shared__ int           s_is64;

    // ---- PDL prologue: independent of k1's outputs ----
    detect_is64(lab_raw, t, &s_is64);
    if (t < LL) {
        s_fj[t]     = NONE;
        s_colwin[t] = NONE;
    }
    __syncthreads();
    if (t < LRR) {
        s_lab[t] = s_is64 ? lab_raw[(b * LRR + t) * 2] : lab_raw[b * LRR + t];
    }

    // ---- Wait for k1 grid completion (g_hard/g_probs now visible) ----
    cudaGridDependencySynchronize();

    // Front-issue ALL global loads: 4x float4 probs quads + g_hard.
    // Thread t owns cells 4t..4t+3 of each 4096-cell quarter (coalesced LDG.128;
    // j is constant within a quad since (4t)&127 <= 124).
    const float4* __restrict__ pb4 =
        (const float4*)(g_probs + b * LL * LRR);
    float4 p0 = __ldg(&pb4[t]);
    float4 p1 = __ldg(&pb4[1024 + t]);
    float4 p2 = __ldg(&pb4[2048 + t]);
    float4 p3 = __ldg(&pb4[3072 + t]);
    if (t < LL) s_hard[t] = g_hard[b * LL + t];
    __syncthreads();

    // ---- Sudoku (latency of the loads above hides under these phases) ----
    // Row-first: scan 16384 (i,j) cells, 16 per thread. i fast (stride-1 LDS),
    // s_hard[j] broadcast. atomicMin keeps smallest j per row.
    #pragma unroll
    for (int c = 0; c < LL * LRR; c += 1024) {
        int cell = c + t;
        int i = cell & 127, j = cell >> 7;
        if (s_hard[j] == s_lab[i]) atomicMin(&s_fj[i], j);
    }
    __syncthreads();
    if (t < LRR) {
        int fj = s_fj[t];
        if (fj != NONE) atomicMin(&s_colwin[fj], t);   // column winner = min i
    }
    __syncthreads();
    if (t < LRR) {
        int fj = s_fj[t];
        s_sel[t] = (unsigned char)(fj != NONE && s_colwin[fj] == t);
    }
    __syncthreads();

    // ---- Apply weights to the already-resident quads ----
    // Weights: 1.0 selected; 0.5 both-row-and-col unmatched; 0.1 otherwise.
    const int i0 = (4 * t) & 127;          // first row index of each quad
    float acc = 0.0f;
    {
        const uchar4 sel4 = *(const uchar4*)&s_sel[i0];   // 16B/4B aligned LDS
        const int4   fj4  = *(const int4*)&s_fj[i0];
        #pragma unroll
        for (int q = 0; q < 4; q++) {
            const float4 p = (q == 0) ? p0 : (q == 1) ? p1 : (q == 2) ? p2 : p3;
            const int j = (q * 4096 + 4 * t) >> 7;        // constant per quad
            const bool colUnm = (s_colwin[j] == NONE);
            const float wU = colUnm ? 0.5f : 0.1f;
            acc += (sel4.x ? (fj4.x == j ? 1.0f : 0.1f) : wU) * p.x;
            acc += (sel4.y ? (fj4.y == j ? 1.0f : 0.1f) : wU) * p.y;
            acc += (sel4.z ? (fj4.z == j ? 1.0f : 0.1f) : wU) * p.z;
            acc += (sel4.w ? (fj4.w == j ? 1.0f : 0.1f) : wU) * p.w;
        }
    }

    // Block reduce (deterministic order)
    #pragma unroll
    for (int off = 16; off; off >>= 1)
        acc += __shfl_down_sync(0xffffffffu, acc, off);
    if ((t & 31) == 0) s_red[t >> 5] = acc;
    __syncthreads();
    if (t == 0) {
        float s = 0.0f;
        #pragma unroll
        for (int q = 0; q < 32; q++) s += s_red[q];
        g_partial[b] = s;
        __threadfence();                   // release partial before ticket
        unsigned ticket = atomicAdd(&g_fin, 1u);
        if (ticket == BB - 1) {
            __threadfence();               // acquire all partials
            float tot = 0.0f;
            #pragma unroll
            for (int q = 0; q < BB; q++) tot += g_partial[q];
            out[0] = 1.0f - tot * (1.0f / 2048.0f);   // 1 + mean(-2*tot_b/256)
            g_fin = 0;                     // reset for next graph replay
        }
    }
}

extern "C" void kernel_launch(void* const* d_in, const int* in_sizes, int n_in,
                              void* d_out, int out_size) {
    // Resolve input order by element count (logits: 65.5M; labels: 2048/4096 words)
    int li = (in_sizes[0] > in_sizes[1]) ? 0 : 1;
    const float* logits = (const float*)d_in[li];
    const int*   labels = (const int*)d_in[1 - li];

    k1<<<BB * LL, 256>>>(logits, labels);

    // k2 via PDL: prologue may run while k1 streams; gridsync gates the rest.
    cudaLaunchAttribute attrs[1];
    attrs[0].id = cudaLaunchAttributeProgrammaticStreamSerialization;
    attrs[0].val.programmaticStreamSerializationAllowed = 1;
    cudaLaunchConfig_t cfg = {};
    cfg.gridDim  = dim3(BB, 1, 1);
    cfg.blockDim = dim3(1024, 1, 1);
    cfg.dynamicSmemBytes = 0;
    cfg.stream   = 0;
    cfg.attrs    = attrs;
    cfg.numAttrs = 1;
    cudaLaunchKernelEx(&cfg, k2, labels, (float*)d_out);
}